// round 11
// baseline (speedup 1.0000x reference)
#include <cuda_runtime.h>
#include <math.h>

#define N_TS 8192
#define N_LC 12288
#define NB   64
#define TSB  128
#define LCB  192
#define H    16
#define ROWP 20

// ---------------- global scratch ----------------
__device__ float g_ts_enc[N_TS * H];
__device__ float g_u_ts [N_TS * H];
__device__ float g_lc_enc[N_LC * H];
__device__ float g_u_lc [N_LC * H];
__device__ float g_v_lc [N_LC * H];
__device__ float g_nrm_lc[N_LC];
__device__ float g_f1  [N_LC * H];
__device__ float g_v3  [N_LC * H];
__device__ float g_nrm3[N_LC];
__device__ float g_f2  [N_TS * H];
__device__ float g_u3  [N_TS * H];
__device__ float g_part[NB * 8 * H];
__device__ int   g_cnt [NB];

__device__ __forceinline__ float eluf(float x) { return x > 0.f ? x : expm1f(x); }

__device__ __forceinline__ void ld16s(float (&x)[H], const float* p) {
    const float4* p4 = (const float4*)p;
    #pragma unroll
    for (int q = 0; q < 4; q++) {
        float4 v = p4[q];
        x[4*q] = v.x; x[4*q+1] = v.y; x[4*q+2] = v.z; x[4*q+3] = v.w;
    }
}
__device__ __forceinline__ void ld16g(float (&x)[H], const float* p) {
    const float4* p4 = (const float4*)p;
    #pragma unroll
    for (int q = 0; q < 4; q++) {
        float4 v = __ldg(&p4[q]);
        x[4*q] = v.x; x[4*q+1] = v.y; x[4*q+2] = v.z; x[4*q+3] = v.w;
    }
}

__device__ __forceinline__ float distf(const float (&xi)[H], float nd,
                                       const float* __restrict__ sp, float nj)
{
    const float4* p4 = (const float4*)sp;
    float4 p0 = p4[0], p1 = p4[1], p2 = p4[2], p3 = p4[3];
    float d0 = fmaf(xi[0],  p0.x, fmaf(xi[1],  p0.y, fmaf(xi[2],  p0.z, xi[3]  * p0.w)));
    float d1 = fmaf(xi[4],  p1.x, fmaf(xi[5],  p1.y, fmaf(xi[6],  p1.z, xi[7]  * p1.w)));
    float d2 = fmaf(xi[8],  p2.x, fmaf(xi[9],  p2.y, fmaf(xi[10], p2.z, xi[11] * p2.w)));
    float d3 = fmaf(xi[12], p3.x, fmaf(xi[13], p3.y, fmaf(xi[14], p3.z, xi[15] * p3.w)));
    float dot = __fadd_rn(__fadd_rn(d0, d1), __fadd_rn(d2, d3));
    return fmaf(-2.0f, dot, __fadd_rn(nd, nj));
}

__device__ __forceinline__ float norm16(const float (&x)[H]) {
    float n0 = fmaf(x[0],  x[0],  fmaf(x[1],  x[1],  fmaf(x[2],  x[2],  x[3]  * x[3])));
    float n1 = fmaf(x[4],  x[4],  fmaf(x[5],  x[5],  fmaf(x[6],  x[6],  x[7]  * x[7])));
    float n2 = fmaf(x[8],  x[8],  fmaf(x[9],  x[9],  fmaf(x[10], x[10], x[11] * x[11])));
    float n3 = fmaf(x[12], x[12], fmaf(x[13], x[13], fmaf(x[14], x[14], x[15] * x[15])));
    return (n0 + n1) + (n2 + n3);
}

__device__ __forceinline__ void bitonic16(float (&m)[16]) {
    #pragma unroll
    for (int j = 8; j > 0; j >>= 1) {
        #pragma unroll
        for (int i = 0; i < 16; i++) {
            if ((i & j) == 0) {
                float lo = fminf(m[i], m[i + j]);
                m[i + j] = fmaxf(m[i], m[i + j]);
                m[i] = lo;
            }
        }
    }
}

template<int NT>
__device__ __forceinline__ float pass1_T8(const float (&xi)[H], float nd,
                                          const float* __restrict__ s_enc,
                                          const float* __restrict__ s_nrm,
                                          float* __restrict__ s_d,
                                          int oct, int t)
{
    float bd[16];
    #pragma unroll
    for (int k = 0; k < 16; k++) bd[k] = 1e30f;
    #pragma unroll 2
    for (int j = 0; j < 24; j++) {
        int row = (j << 3) | oct;
        float d = distf(xi, nd, s_enc + row * ROWP, s_nrm[row]);
        s_d[j * NT + t] = d;
        #pragma unroll
        for (int k = 0; k < 16; k++) {
            float lo = fminf(d, bd[k]);
            d = fmaxf(d, bd[k]);
            bd[k] = lo;
        }
    }
    float m[16];
    #pragma unroll
    for (int k = 0; k < 16; k++)
        m[k] = fminf(bd[k], __shfl_xor_sync(0xFFFFFFFFu, bd[15 - k], 1));
    bitonic16(m);
    #pragma unroll
    for (int k = 0; k < 16; k++)
        bd[k] = fminf(m[k], __shfl_xor_sync(0xFFFFFFFFu, m[15 - k], 2));
    bitonic16(bd);
    float T = -1e30f;
    #pragma unroll
    for (int k = 0; k < 16; k++)
        T = fmaxf(T, fminf(bd[k], __shfl_xor_sync(0xFFFFFFFFu, bd[15 - k], 4)));
    return T;
}

template<int NT>
__device__ __forceinline__ void select_maxv8(float T,
                                             const float* __restrict__ s_d,
                                             const float* __restrict__ s_v,
                                             int* __restrict__ s_cnt,
                                             int* __restrict__ s_sel,
                                             int dl, int oct, int t, float (&mv)[H])
{
    #pragma unroll 4
    for (int j = 0; j < 24; j++) {
        float d = s_d[j * NT + t];
        if (d <= T) {
            int p = atomicAdd(&s_cnt[dl], 1);
            if (p < 24) s_sel[dl * 24 + p] = (j << 3) | oct;
        }
    }
    __syncwarp();
    #pragma unroll
    for (int h = 0; h < H; h++) mv[h] = -1e30f;
    int n = s_cnt[dl]; if (n > 24) n = 24;
    for (int k = oct; k < n; k += 8) {
        int row = s_sel[dl * 24 + k];
        const float4* v4 = (const float4*)(s_v + row * ROWP);
        float4 q0 = v4[0], q1 = v4[1], q2 = v4[2], q3 = v4[3];
        mv[0]  = fmaxf(mv[0],  q0.x); mv[1]  = fmaxf(mv[1],  q0.y);
        mv[2]  = fmaxf(mv[2],  q0.z); mv[3]  = fmaxf(mv[3],  q0.w);
        mv[4]  = fmaxf(mv[4],  q1.x); mv[5]  = fmaxf(mv[5],  q1.y);
        mv[6]  = fmaxf(mv[6],  q1.z); mv[7]  = fmaxf(mv[7],  q1.w);
        mv[8]  = fmaxf(mv[8],  q2.x); mv[9]  = fmaxf(mv[9],  q2.y);
        mv[10] = fmaxf(mv[10], q2.z); mv[11] = fmaxf(mv[11], q2.w);
        mv[12] = fmaxf(mv[12], q3.x); mv[13] = fmaxf(mv[13], q3.y);
        mv[14] = fmaxf(mv[14], q3.z); mv[15] = fmaxf(mv[15], q3.w);
    }
    #pragma unroll
    for (int h = 0; h < H; h++) mv[h] = fmaxf(mv[h], __shfl_xor_sync(0xFFFFFFFFu, mv[h], 1));
    #pragma unroll
    for (int h = 0; h < H; h++) mv[h] = fmaxf(mv[h], __shfl_xor_sync(0xFFFFFFFFu, mv[h], 2));
    #pragma unroll
    for (int h = 0; h < H; h++) mv[h] = fmaxf(mv[h], __shfl_xor_sync(0xFFFFFFFFu, mv[h], 4));
}

// ==================== K0: encoders — lane-per-channel + smem activation handoff ====================
// smem weight layout (floats):
//   0: tw1(96) | 96: tb1(16) | 112: tw2(256) | 368: tb2(16)
// 384: lw1(80) | 464: lb1(16)| 480: lw2(256) | 736: lb2(16)
// 752: cw(512) | 1264: cb(16)   total 1280 floats
__global__ void __launch_bounds__(256)
k_encode(const float* __restrict__ x_ts, const float* __restrict__ x_lc,
         const float* __restrict__ tw1, const float* __restrict__ tb1,
         const float* __restrict__ tw2, const float* __restrict__ tb2,
         const float* __restrict__ lw1, const float* __restrict__ lb1,
         const float* __restrict__ lw2, const float* __restrict__ lb2,
         const float* __restrict__ cw,  const float* __restrict__ cb)
{
    __shared__ float s_ew[1280];
    __shared__ float s_act[16 * 17];   // 16 points/block, padded rows
    const int t = threadIdx.x;
    for (int i = t; i < 1280; i += 256) {
        float val;
        if      (i < 96)   val = __ldg(&tw1[i]);
        else if (i < 112)  val = __ldg(&tb1[i - 96]);
        else if (i < 368)  val = __ldg(&tw2[i - 112]);
        else if (i < 384)  val = __ldg(&tb2[i - 368]);
        else if (i < 464)  val = __ldg(&lw1[i - 384]);
        else if (i < 480)  val = __ldg(&lb1[i - 464]);
        else if (i < 736)  val = __ldg(&lw2[i - 480]);
        else if (i < 752)  val = __ldg(&lb2[i - 736]);
        else if (i < 1264) val = __ldg(&cw[i - 752]);
        else               val = __ldg(&cb[i - 1264]);
        s_ew[i] = val;
    }
    __syncthreads();

    const int gtid = blockIdx.x * 256 + t;
    const int p  = gtid >> 4;       // point id (0..20479)
    const int o  = gtid & 15;       // channel lane
    const int pl = t >> 4;          // local point slot (0..15)
    float* act = &s_act[pl * 17];
    if (gtid < NB) g_cnt[gtid] = 0; // reset pool tickets for kB
    const unsigned FULL = 0xFFFFFFFFu;

    if (p < N_TS) {
        // ---- TS point ----
        float xv = (o < 6) ? __ldg(&x_ts[p * 6 + o]) : 0.f;
        act[o] = xv;
        __syncwarp(FULL);
        float a = s_ew[96 + o];
        #pragma unroll
        for (int i = 0; i < 6; i++) a = fmaf(act[i], s_ew[i * H + o], a);
        float h1 = eluf(a);
        __syncwarp(FULL);
        act[o] = h1;
        __syncwarp(FULL);

        float a0 = s_ew[368 + o], a1 = 0.f, a2 = 0.f, a3 = 0.f;
        #pragma unroll
        for (int r = 0; r < 4; r++) {
            a0 = fmaf(act[r],      s_ew[112 + (r)      * H + o], a0);
            a1 = fmaf(act[4 + r],  s_ew[112 + (4 + r)  * H + o], a1);
            a2 = fmaf(act[8 + r],  s_ew[112 + (8 + r)  * H + o], a2);
            a3 = fmaf(act[12 + r], s_ew[112 + (12 + r) * H + o], a3);
        }
        float e = eluf((a0 + a1) + (a2 + a3));
        g_ts_enc[p * H + o] = e;
        __syncwarp(FULL);
        act[o] = e;
        __syncwarp(FULL);

        float u0 = s_ew[1264 + o], u1 = 0.f, u2 = 0.f, u3 = 0.f;
        #pragma unroll
        for (int r = 0; r < 4; r++) {
            u0 = fmaf(act[r],      s_ew[752 + (r)      * H + o] - s_ew[752 + (H + r)      * H + o], u0);
            u1 = fmaf(act[4 + r],  s_ew[752 + (4 + r)  * H + o] - s_ew[752 + (H + 4 + r)  * H + o], u1);
            u2 = fmaf(act[8 + r],  s_ew[752 + (8 + r)  * H + o] - s_ew[752 + (H + 8 + r)  * H + o], u2);
            u3 = fmaf(act[12 + r], s_ew[752 + (12 + r) * H + o] - s_ew[752 + (H + 12 + r) * H + o], u3);
        }
        g_u_ts[p * H + o] = (u0 + u1) + (u2 + u3);
    } else if (p < N_TS + N_LC) {
        // ---- LC point ----
        const int id = p - N_TS;
        float xv = (o < 5) ? __ldg(&x_lc[id * 5 + o]) : 0.f;
        act[o] = xv;
        __syncwarp(FULL);
        float a = s_ew[464 + o];
        #pragma unroll
        for (int i = 0; i < 5; i++) a = fmaf(act[i], s_ew[384 + i * H + o], a);
        float h1 = eluf(a);
        __syncwarp(FULL);
        act[o] = h1;
        __syncwarp(FULL);

        float a0 = s_ew[736 + o], a1 = 0.f, a2 = 0.f, a3 = 0.f;
        #pragma unroll
        for (int r = 0; r < 4; r++) {
            a0 = fmaf(act[r],      s_ew[480 + (r)      * H + o], a0);
            a1 = fmaf(act[4 + r],  s_ew[480 + (4 + r)  * H + o], a1);
            a2 = fmaf(act[8 + r],  s_ew[480 + (8 + r)  * H + o], a2);
            a3 = fmaf(act[12 + r], s_ew[480 + (12 + r) * H + o], a3);
        }
        float e = eluf((a0 + a1) + (a2 + a3));
        g_lc_enc[id * H + o] = e;

        // norm over the 16 lanes (independent of s_act)
        float r = e * e;
        r += __shfl_xor_sync(FULL, r, 1, 16);
        r += __shfl_xor_sync(FULL, r, 2, 16);
        r += __shfl_xor_sync(FULL, r, 4, 16);
        r += __shfl_xor_sync(FULL, r, 8, 16);
        if (o == 0) g_nrm_lc[id] = r;

        __syncwarp(FULL);
        act[o] = e;
        __syncwarp(FULL);

        float u0 = s_ew[1264 + o], u1 = 0.f, u2 = 0.f, u3 = 0.f;
        float v0 = 0.f, v1 = 0.f, v2 = 0.f, v3 = 0.f;
        #pragma unroll
        for (int r2 = 0; r2 < 4; r2++) {
            float e0 = act[r2],      wtb0 = s_ew[752 + (H + r2)      * H + o];
            float e1 = act[4 + r2],  wtb1 = s_ew[752 + (H + 4 + r2)  * H + o];
            float e2 = act[8 + r2],  wtb2 = s_ew[752 + (H + 8 + r2)  * H + o];
            float e3 = act[12 + r2], wtb3 = s_ew[752 + (H + 12 + r2) * H + o];
            u0 = fmaf(e0, s_ew[752 + (r2)      * H + o] - wtb0, u0);
            u1 = fmaf(e1, s_ew[752 + (4 + r2)  * H + o] - wtb1, u1);
            u2 = fmaf(e2, s_ew[752 + (8 + r2)  * H + o] - wtb2, u2);
            u3 = fmaf(e3, s_ew[752 + (12 + r2) * H + o] - wtb3, u3);
            v0 = fmaf(e0, wtb0, v0);
            v1 = fmaf(e1, wtb1, v1);
            v2 = fmaf(e2, wtb2, v2);
            v3 = fmaf(e3, wtb3, v3);
        }
        g_u_lc[id * H + o] = (u0 + u1) + (u2 + u3);
        g_v_lc[id * H + o] = (v0 + v1) + (v2 + v3);
    }
}

// ================= kA: conv1 + conv2 (+u3/v3 fused), 32 dst x 8 thr =================
#define A_ENC 0
#define A_V   3840
#define A_NRM 7680
#define A_W   7872
#define A_B   8384
#define A_D   8400
#define A_F   14544
#define A_CNT 15184
#define A_SEL 15216
#define A_TOTF 15984   // 63936 bytes

__global__ void __launch_bounds__(256, 3)
kA(const float* __restrict__ cw, const float* __restrict__ cb)
{
    extern __shared__ float sm[];
    float* s_enc = sm + A_ENC;
    float* s_v   = sm + A_V;
    float* s_nrm = sm + A_NRM;
    float* s_w   = sm + A_W;
    float* s_b   = sm + A_B;
    float* s_d   = sm + A_D;
    float* s_f   = sm + A_F;
    int*   s_cnt = (int*)(sm + A_CNT);
    int*   s_sel = (int*)(sm + A_SEL);

    const int g = blockIdx.x / 10, part = blockIdx.x % 10;
    const int t = threadIdx.x;
    const bool isLC = part < 6;

    {
        const float4* ge = (const float4*)(g_lc_enc + g * LCB * H);
        const float4* gv = (const float4*)(g_v_lc  + g * LCB * H);
        float4* se = (float4*)s_enc; float4* sv = (float4*)s_v;
        #pragma unroll
        for (int i = t; i < LCB * 4; i += 256) {
            int r = i >> 2, c = i & 3;
            se[r * 5 + c] = __ldg(&ge[i]);
            sv[r * 5 + c] = __ldg(&gv[i]);
        }
        if (t < LCB) s_nrm[t] = __ldg(&g_nrm_lc[g * LCB + t]);
        for (int i = t; i < 512; i += 256) s_w[i] = __ldg(&cw[i]);
        if (t < 16) s_b[t] = __ldg(&cb[t]);
        if (t < 32) s_cnt[t] = 0;
    }
    __syncthreads();

    const int dl = t >> 3, oct = t & 7;
    const int dstRow = isLC ? g * LCB + part * 32 + dl
                            : g * TSB + (part - 6) * 32 + dl;
    float xi[H];
    if (isLC) ld16s(xi, s_enc + (part * 32 + dl) * ROWP);
    else      ld16g(xi, g_ts_enc + dstRow * H);
    float nd = norm16(xi);

    float T = pass1_T8<256>(xi, nd, s_enc, s_nrm, s_d, oct, t);
    float mv[H];
    select_maxv8<256>(T, s_d, s_v, s_cnt, s_sel, dl, oct, t, mv);

    const int ch0 = oct * 2;
    const float* uPtr = (isLC ? g_u_lc : g_u_ts) + dstRow * H;
    float u0 = __ldg(&uPtr[ch0]), u1 = __ldg(&uPtr[ch0 + 1]);
    float fa = eluf(u0 + mv[ch0]), fb = eluf(u1 + mv[ch0 + 1]);
    s_f[dl * ROWP + ch0] = fa; s_f[dl * ROWP + ch0 + 1] = fb;
    __syncwarp();
    float f[H];
    ld16s(f, s_f + dl * ROWP);

    if (isLC) {
        *(float2*)&g_f1[dstRow * H + ch0] = make_float2(fa, fb);
        float a0 = 0.f, a1 = 0.f;
        #pragma unroll
        for (int i = 0; i < H; i++) {
            a0 = fmaf(f[i], s_w[(H + i) * H + ch0], a0);
            a1 = fmaf(f[i], s_w[(H + i) * H + ch0 + 1], a1);
        }
        *(float2*)&g_v3[dstRow * H + ch0] = make_float2(a0, a1);
        if (oct == 0) g_nrm3[dstRow] = norm16(f);
    } else {
        *(float2*)&g_f2[dstRow * H + ch0] = make_float2(fa, fb);
        float a0 = s_b[ch0], a1 = s_b[ch0 + 1];
        #pragma unroll
        for (int i = 0; i < H; i++) {
            a0 = fmaf(f[i], s_w[i * H + ch0] - s_w[(H + i) * H + ch0], a0);
            a1 = fmaf(f[i], s_w[i * H + ch0 + 1] - s_w[(H + i) * H + ch0 + 1], a1);
        }
        *(float2*)&g_u3[dstRow * H + ch0] = make_float2(a0, a1);
    }
}

// ================= kB: conv3 + pool + head, 16 dst x 8 thr =================
#define B_ENC  0
#define B_V    3840
#define B_NRM  7680
#define B_D    7872
#define B_POOL 10944
#define B_PLD  11264
#define B_H1   11280
#define B_H2   11344
#define B_H3   11376
#define B_H4   11384
#define B_CNT  11388
#define B_SEL  11404
#define B_FLAG 11788
#define B_TOTF 11792   // 47168 bytes

__global__ void __launch_bounds__(128, 4)
kB(const float* __restrict__ w1, const float* __restrict__ b1,
   const float* __restrict__ w2, const float* __restrict__ b2,
   const float* __restrict__ w3, const float* __restrict__ b3,
   const float* __restrict__ w4, const float* __restrict__ b4,
   const float* __restrict__ w5, const float* __restrict__ b5,
   float* __restrict__ out, int out_size)
{
    extern __shared__ float sm[];
    float* s_enc  = sm + B_ENC;
    float* s_v    = sm + B_V;
    float* s_nrm  = sm + B_NRM;
    float* s_d    = sm + B_D;
    float* s_pool = sm + B_POOL;
    float* pooled = sm + B_PLD;
    float* h1s    = sm + B_H1;
    float* h2s    = sm + B_H2;
    float* h3s    = sm + B_H3;
    float* h4s    = sm + B_H4;
    int*   s_cnt  = (int*)(sm + B_CNT);
    int*   s_sel  = (int*)(sm + B_SEL);
    int*   s_flag = (int*)(sm + B_FLAG);

    const int g = blockIdx.x >> 3, qpart = blockIdx.x & 7;
    const int t = threadIdx.x;

    {
        const float4* ge = (const float4*)(g_f1 + g * LCB * H);
        const float4* gv = (const float4*)(g_v3 + g * LCB * H);
        float4* se = (float4*)s_enc; float4* sv = (float4*)s_v;
        #pragma unroll
        for (int i = t; i < LCB * 4; i += 128) {
            int r = i >> 2, c = i & 3;
            se[r * 5 + c] = __ldg(&ge[i]);
            sv[r * 5 + c] = __ldg(&gv[i]);
        }
        for (int i = t; i < LCB; i += 128) s_nrm[i] = __ldg(&g_nrm3[g * LCB + i]);
        if (t < 16) s_cnt[t] = 0;
    }
    __syncthreads();

    const int dl = t >> 3, oct = t & 7;
    const int dstRow = g * TSB + qpart * 16 + dl;
    float xi[H];
    ld16g(xi, g_f2 + dstRow * H);
    float nd = norm16(xi);

    float T = pass1_T8<128>(xi, nd, s_enc, s_nrm, s_d, oct, t);
    float mv[H];
    select_maxv8<128>(T, s_d, s_v, s_cnt, s_sel, dl, oct, t, mv);

    const int ch0 = oct * 2;
    float u0 = __ldg(&g_u3[dstRow * H + ch0]), u1 = __ldg(&g_u3[dstRow * H + ch0 + 1]);
    s_pool[dl * ROWP + ch0]     = eluf(u0 + mv[ch0]);
    s_pool[dl * ROWP + ch0 + 1] = eluf(u1 + mv[ch0 + 1]);
    __syncthreads();

    if (t < H) {
        float a = 0.f;
        #pragma unroll
        for (int d = 0; d < 16; d++) a += s_pool[d * ROWP + t];
        g_part[(g * 8 + qpart) * H + t] = a;
    }
    __threadfence();
    __syncthreads();
    if (t == 0) {
        int tk = atomicAdd(&g_cnt[g], 1);
        s_flag[0] = (tk == 7);
    }
    __syncthreads();

    if (s_flag[0]) {
        __threadfence();
        if (t < H) {
            const float* pp = g_part + g * 8 * H + t;
            float p01 = pp[0] + pp[H];
            float p23 = pp[2*H] + pp[3*H];
            float p45 = pp[4*H] + pp[5*H];
            float p67 = pp[6*H] + pp[7*H];
            pooled[t] = ((p01 + p23) + (p45 + p67)) * (1.f / (float)TSB);
        }
        __syncthreads();
        if (t < 64) {
            float sv = __ldg(&b1[t]);
            #pragma unroll
            for (int i = 0; i < H; i++) sv += pooled[i] * __ldg(&w1[i * 64 + t]);
            h1s[t] = eluf(sv);
        }
        __syncthreads();
        if (t < 32) {
            float sv = __ldg(&b2[t]);
            #pragma unroll
            for (int i = 0; i < 64; i++) sv += h1s[i] * __ldg(&w2[i * 32 + t]);
            h2s[t] = eluf(sv);
        }
        __syncthreads();
        if (t < 8) {
            float sv = __ldg(&b3[t]);
            #pragma unroll
            for (int i = 0; i < 32; i++) sv += h2s[i] * __ldg(&w3[i * 8 + t]);
            h3s[t] = eluf(sv);
        }
        __syncthreads();
        if (t < 4) {
            float sv = __ldg(&b4[t]);
            #pragma unroll
            for (int i = 0; i < 8; i++) sv += h3s[i] * __ldg(&w4[i * 4 + t]);
            h4s[t] = eluf(sv);
        }
        __syncthreads();
        if (t == 0) {
            float sv = __ldg(&b5[0]);
            #pragma unroll
            for (int i = 0; i < 4; i++) sv += h4s[i] * __ldg(&w5[i]);
            if (g < out_size) out[g] = sv;
            if (NB + g < out_size) out[NB + g] = (float)g;
        }
    }
}

// ==================== launch ====================
extern "C" void kernel_launch(void* const* d_in, const int* in_sizes, int n_in,
                              void* d_out, int out_size)
{
    const float* x_ts = (const float*)d_in[0];
    const float* x_lc = (const float*)d_in[1];
    const float* tw1 = (const float*)d_in[4];
    const float* tb1 = (const float*)d_in[5];
    const float* tw2 = (const float*)d_in[6];
    const float* tb2 = (const float*)d_in[7];
    const float* lw1 = (const float*)d_in[8];
    const float* lb1 = (const float*)d_in[9];
    const float* lw2 = (const float*)d_in[10];
    const float* lb2 = (const float*)d_in[11];
    const float* cw  = (const float*)d_in[12];
    const float* cb  = (const float*)d_in[13];
    const float* w1  = (const float*)d_in[14];
    const float* b1  = (const float*)d_in[15];
    const float* w2  = (const float*)d_in[16];
    const float* b2  = (const float*)d_in[17];
    const float* w3  = (const float*)d_in[18];
    const float* b3  = (const float*)d_in[19];
    const float* w4  = (const float*)d_in[20];
    const float* b4  = (const float*)d_in[21];
    const float* w5  = (const float*)d_in[22];
    const float* b5  = (const float*)d_in[23];

    cudaFuncSetAttribute(kA, cudaFuncAttributeMaxDynamicSharedMemorySize, A_TOTF * 4);
    cudaFuncSetAttribute(kB, cudaFuncAttributeMaxDynamicSharedMemorySize, B_TOTF * 4);

    // lane-per-channel encode: 16 threads per point
    k_encode<<<((N_TS + N_LC) * 16) / 256, 256>>>(x_ts, x_lc, tw1, tb1, tw2, tb2,
                                                  lw1, lb1, lw2, lb2, cw, cb);
    kA<<<NB * 10, 256, A_TOTF * 4>>>(cw, cb);
    kB<<<NB * 8, 128, B_TOTF * 4>>>(w1, b1, w2, b2, w3, b3, w4, b4, w5, b5,
                                    (float*)d_out, out_size);
}

// round 13
// speedup vs baseline: 1.0484x; 1.0484x over previous
#include <cuda_runtime.h>
#include <math.h>

#define N_TS 8192
#define N_LC 12288
#define NB   64
#define TSB  128
#define LCB  192
#define H    16
#define ROWP 20

typedef unsigned long long u64;

// ---------------- global scratch ----------------
__device__ float g_ts_enc[N_TS * H];
__device__ float g_u_ts [N_TS * H];
__device__ float g_lc_enc[N_LC * H];
__device__ float g_u_lc [N_LC * H];
__device__ float g_v_lc [N_LC * H];
__device__ float g_nrm_lc[N_LC];
__device__ float g_f1  [N_LC * H];
__device__ float g_v3  [N_LC * H];
__device__ float g_nrm3[N_LC];
__device__ float g_f2  [N_TS * H];
__device__ float g_u3  [N_TS * H];
__device__ float g_part[NB * 8 * H];
__device__ int   g_cnt [NB];

__device__ __forceinline__ float eluf(float x) { return x > 0.f ? x : expm1f(x); }

__device__ __forceinline__ void ld16s(float (&x)[H], const float* p) {
    const float4* p4 = (const float4*)p;
    #pragma unroll
    for (int q = 0; q < 4; q++) {
        float4 v = p4[q];
        x[4*q] = v.x; x[4*q+1] = v.y; x[4*q+2] = v.z; x[4*q+3] = v.w;
    }
}
__device__ __forceinline__ void ld16g(float (&x)[H], const float* p) {
    const float4* p4 = (const float4*)p;
    #pragma unroll
    for (int q = 0; q < 4; q++) {
        float4 v = __ldg(&p4[q]);
        x[4*q] = v.x; x[4*q+1] = v.y; x[4*q+2] = v.z; x[4*q+3] = v.w;
    }
}

// ---------------- packed f32x2 helpers ----------------
__device__ __forceinline__ u64 pk2(float a, float b) {
    u64 r; asm("mov.b64 %0, {%1, %2};" : "=l"(r) : "f"(a), "f"(b)); return r;
}
__device__ __forceinline__ float2 upk2(u64 v) {
    float2 r; asm("mov.b64 {%0, %1}, %2;" : "=f"(r.x), "=f"(r.y) : "l"(v)); return r;
}
__device__ __forceinline__ u64 mul2(u64 a, u64 b) {
    u64 r; asm("mul.rn.f32x2 %0, %1, %2;" : "=l"(r) : "l"(a), "l"(b)); return r;
}
__device__ __forceinline__ u64 fma2(u64 a, u64 b, u64 c) {
    u64 r; asm("fma.rn.f32x2 %0, %1, %2, %3;" : "=l"(r) : "l"(a), "l"(b), "l"(c)); return r;
}

// packed distance: 8 FFMA2 (2 chains of 4) instead of 16 FFMA
__device__ __forceinline__ float distp(const u64 (&xp)[8], float nd,
                                       const float* __restrict__ sp, float nj)
{
    const float4* p4 = (const float4*)sp;
    float4 p0 = p4[0], p1 = p4[1], p2 = p4[2], p3 = p4[3];
    u64 a = mul2(xp[0], pk2(p0.x, p0.y));
    a = fma2(xp[1], pk2(p0.z, p0.w), a);
    a = fma2(xp[2], pk2(p1.x, p1.y), a);
    a = fma2(xp[3], pk2(p1.z, p1.w), a);
    u64 b = mul2(xp[4], pk2(p2.x, p2.y));
    b = fma2(xp[5], pk2(p2.z, p2.w), b);
    b = fma2(xp[6], pk2(p3.x, p3.y), b);
    b = fma2(xp[7], pk2(p3.z, p3.w), b);
    float2 fa = upk2(a), fb = upk2(b);
    float dot = __fadd_rn(__fadd_rn(fa.x, fa.y), __fadd_rn(fb.x, fb.y));
    return fmaf(-2.0f, dot, __fadd_rn(nd, nj));
}

__device__ __forceinline__ float norm16(const float (&x)[H]) {
    float n0 = fmaf(x[0],  x[0],  fmaf(x[1],  x[1],  fmaf(x[2],  x[2],  x[3]  * x[3])));
    float n1 = fmaf(x[4],  x[4],  fmaf(x[5],  x[5],  fmaf(x[6],  x[6],  x[7]  * x[7])));
    float n2 = fmaf(x[8],  x[8],  fmaf(x[9],  x[9],  fmaf(x[10], x[10], x[11] * x[11])));
    float n3 = fmaf(x[12], x[12], fmaf(x[13], x[13], fmaf(x[14], x[14], x[15] * x[15])));
    return (n0 + n1) + (n2 + n3);
}

__device__ __forceinline__ void bitonic16(float (&m)[16]) {
    #pragma unroll
    for (int j = 8; j > 0; j >>= 1) {
        #pragma unroll
        for (int i = 0; i < 16; i++) {
            if ((i & j) == 0) {
                float lo = fminf(m[i], m[i + j]);
                m[i + j] = fmaxf(m[i], m[i + j]);
                m[i] = lo;
            }
        }
    }
}

// 8 threads per dst; growing-depth insertion (exact; upper slots are +inf)
template<int NT>
__device__ __forceinline__ float pass1_T8(const u64 (&xp)[8], float nd,
                                          const float* __restrict__ s_enc,
                                          const float* __restrict__ s_nrm,
                                          float* __restrict__ s_d,
                                          int oct, int t)
{
    float bd[16];
    #pragma unroll
    for (int k = 0; k < 16; k++) bd[k] = 1e30f;
    #pragma unroll
    for (int j = 0; j < 16; j++) {
        int row = (j << 3) | oct;
        float d = distp(xp, nd, s_enc + row * ROWP, s_nrm[row]);
        s_d[j * NT + t] = d;
        #pragma unroll
        for (int k = 0; k <= j; k++) {
            float lo = fminf(d, bd[k]);
            d = fmaxf(d, bd[k]);
            bd[k] = lo;
        }
    }
    #pragma unroll 2
    for (int j = 16; j < 24; j++) {
        int row = (j << 3) | oct;
        float d = distp(xp, nd, s_enc + row * ROWP, s_nrm[row]);
        s_d[j * NT + t] = d;
        #pragma unroll
        for (int k = 0; k < 16; k++) {
            float lo = fminf(d, bd[k]);
            d = fmaxf(d, bd[k]);
            bd[k] = lo;
        }
    }
    float m[16];
    #pragma unroll
    for (int k = 0; k < 16; k++)
        m[k] = fminf(bd[k], __shfl_xor_sync(0xFFFFFFFFu, bd[15 - k], 1));
    bitonic16(m);
    #pragma unroll
    for (int k = 0; k < 16; k++)
        bd[k] = fminf(m[k], __shfl_xor_sync(0xFFFFFFFFu, m[15 - k], 2));
    bitonic16(bd);
    float T = -1e30f;
    #pragma unroll
    for (int k = 0; k < 16; k++)
        T = fmaxf(T, fminf(bd[k], __shfl_xor_sync(0xFFFFFFFFu, bd[15 - k], 4)));
    return T;
}

template<int NT>
__device__ __forceinline__ void select_maxv8(float T,
                                             const float* __restrict__ s_d,
                                             const float* __restrict__ s_v,
                                             int* __restrict__ s_cnt,
                                             int* __restrict__ s_sel,
                                             int dl, int oct, int t, float (&mv)[H])
{
    #pragma unroll 4
    for (int j = 0; j < 24; j++) {
        float d = s_d[j * NT + t];
        if (d <= T) {
            int p = atomicAdd(&s_cnt[dl], 1);
            if (p < 24) s_sel[dl * 24 + p] = (j << 3) | oct;
        }
    }
    __syncwarp();
    #pragma unroll
    for (int h = 0; h < H; h++) mv[h] = -1e30f;
    int n = s_cnt[dl]; if (n > 24) n = 24;
    for (int k = oct; k < n; k += 8) {
        int row = s_sel[dl * 24 + k];
        const float4* v4 = (const float4*)(s_v + row * ROWP);
        float4 q0 = v4[0], q1 = v4[1], q2 = v4[2], q3 = v4[3];
        mv[0]  = fmaxf(mv[0],  q0.x); mv[1]  = fmaxf(mv[1],  q0.y);
        mv[2]  = fmaxf(mv[2],  q0.z); mv[3]  = fmaxf(mv[3],  q0.w);
        mv[4]  = fmaxf(mv[4],  q1.x); mv[5]  = fmaxf(mv[5],  q1.y);
        mv[6]  = fmaxf(mv[6],  q1.z); mv[7]  = fmaxf(mv[7],  q1.w);
        mv[8]  = fmaxf(mv[8],  q2.x); mv[9]  = fmaxf(mv[9],  q2.y);
        mv[10] = fmaxf(mv[10], q2.z); mv[11] = fmaxf(mv[11], q2.w);
        mv[12] = fmaxf(mv[12], q3.x); mv[13] = fmaxf(mv[13], q3.y);
        mv[14] = fmaxf(mv[14], q3.z); mv[15] = fmaxf(mv[15], q3.w);
    }
    #pragma unroll
    for (int h = 0; h < H; h++) mv[h] = fmaxf(mv[h], __shfl_xor_sync(0xFFFFFFFFu, mv[h], 1));
    #pragma unroll
    for (int h = 0; h < H; h++) mv[h] = fmaxf(mv[h], __shfl_xor_sync(0xFFFFFFFFu, mv[h], 2));
    #pragma unroll
    for (int h = 0; h < H; h++) mv[h] = fmaxf(mv[h], __shfl_xor_sync(0xFFFFFFFFu, mv[h], 4));
}

// ==================== K0: encoders — lane-per-channel ====================
__global__ void __launch_bounds__(256)
k_encode(const float* __restrict__ x_ts, const float* __restrict__ x_lc,
         const float* __restrict__ tw1, const float* __restrict__ tb1,
         const float* __restrict__ tw2, const float* __restrict__ tb2,
         const float* __restrict__ lw1, const float* __restrict__ lb1,
         const float* __restrict__ lw2, const float* __restrict__ lb2,
         const float* __restrict__ cw,  const float* __restrict__ cb)
{
    __shared__ float s_ew[1280];
    const int t = threadIdx.x;
    for (int i = t; i < 1280; i += 256) {
        float val;
        if      (i < 96)   val = __ldg(&tw1[i]);
        else if (i < 112)  val = __ldg(&tb1[i - 96]);
        else if (i < 368)  val = __ldg(&tw2[i - 112]);
        else if (i < 384)  val = __ldg(&tb2[i - 368]);
        else if (i < 464)  val = __ldg(&lw1[i - 384]);
        else if (i < 480)  val = __ldg(&lb1[i - 464]);
        else if (i < 736)  val = __ldg(&lw2[i - 480]);
        else if (i < 752)  val = __ldg(&lb2[i - 736]);
        else if (i < 1264) val = __ldg(&cw[i - 752]);
        else               val = __ldg(&cb[i - 1264]);
        s_ew[i] = val;
    }
    __syncthreads();

    const int gtid = blockIdx.x * 256 + t;
    const int p = gtid >> 4;        // point id
    const int o = gtid & 15;        // channel lane
    if (gtid < NB) g_cnt[gtid] = 0; // reset pool tickets for kB
    const unsigned FULL = 0xFFFFFFFFu;

    if (p < N_TS) {
        float xv = (o < 6) ? __ldg(&x_ts[p * 6 + o]) : 0.f;
        float acc = s_ew[96 + o];
        #pragma unroll
        for (int i = 0; i < 6; i++)
            acc = fmaf(__shfl_sync(FULL, xv, i, 16), s_ew[i * H + o], acc);
        float h1 = eluf(acc);

        acc = s_ew[368 + o];
        #pragma unroll
        for (int i = 0; i < H; i++)
            acc = fmaf(__shfl_sync(FULL, h1, i, 16), s_ew[112 + i * H + o], acc);
        float e = eluf(acc);
        g_ts_enc[p * H + o] = e;

        float uacc = s_ew[1264 + o];
        #pragma unroll
        for (int i = 0; i < H; i++) {
            float ei = __shfl_sync(FULL, e, i, 16);
            uacc = fmaf(ei, s_ew[752 + i * H + o] - s_ew[752 + (H + i) * H + o], uacc);
        }
        g_u_ts[p * H + o] = uacc;
    } else if (p < N_TS + N_LC) {
        const int id = p - N_TS;
        float xv = (o < 5) ? __ldg(&x_lc[id * 5 + o]) : 0.f;
        float acc = s_ew[464 + o];
        #pragma unroll
        for (int i = 0; i < 5; i++)
            acc = fmaf(__shfl_sync(FULL, xv, i, 16), s_ew[384 + i * H + o], acc);
        float h1 = eluf(acc);

        acc = s_ew[736 + o];
        #pragma unroll
        for (int i = 0; i < H; i++)
            acc = fmaf(__shfl_sync(FULL, h1, i, 16), s_ew[480 + i * H + o], acc);
        float e = eluf(acc);
        g_lc_enc[id * H + o] = e;

        float r = e * e;
        r += __shfl_xor_sync(FULL, r, 1, 16);
        r += __shfl_xor_sync(FULL, r, 2, 16);
        r += __shfl_xor_sync(FULL, r, 4, 16);
        r += __shfl_xor_sync(FULL, r, 8, 16);
        if (o == 0) g_nrm_lc[id] = r;

        float uacc = s_ew[1264 + o], vacc = 0.f;
        #pragma unroll
        for (int i = 0; i < H; i++) {
            float ei = __shfl_sync(FULL, e, i, 16);
            float wt = s_ew[752 + i * H + o];
            float wb = s_ew[752 + (H + i) * H + o];
            uacc = fmaf(ei, wt - wb, uacc);
            vacc = fmaf(ei, wb, vacc);
        }
        g_u_lc[id * H + o] = uacc;
        g_v_lc[id * H + o] = vacc;
    }
}

// ================= kA: conv1 + conv2 (+u3/v3 fused), 32 dst x 8 thr =================
#define A_ENC 0
#define A_V   3840
#define A_NRM 7680
#define A_W   7872
#define A_B   8384
#define A_D   8400
#define A_F   14544
#define A_CNT 15184
#define A_SEL 15216
#define A_TOTF 15984   // 63936 bytes

__global__ void __launch_bounds__(256, 3)
kA(const float* __restrict__ cw, const float* __restrict__ cb)
{
    extern __shared__ float sm[];
    float* s_enc = sm + A_ENC;
    float* s_v   = sm + A_V;
    float* s_nrm = sm + A_NRM;
    float* s_w   = sm + A_W;
    float* s_b   = sm + A_B;
    float* s_d   = sm + A_D;
    float* s_f   = sm + A_F;
    int*   s_cnt = (int*)(sm + A_CNT);
    int*   s_sel = (int*)(sm + A_SEL);

    const int g = blockIdx.x / 10, part = blockIdx.x % 10;
    const int t = threadIdx.x;
    const bool isLC = part < 6;

    {
        const float4* ge = (const float4*)(g_lc_enc + g * LCB * H);
        const float4* gv = (const float4*)(g_v_lc  + g * LCB * H);
        float4* se = (float4*)s_enc; float4* sv = (float4*)s_v;
        #pragma unroll
        for (int i = t; i < LCB * 4; i += 256) {
            int r = i >> 2, c = i & 3;
            se[r * 5 + c] = __ldg(&ge[i]);
            sv[r * 5 + c] = __ldg(&gv[i]);
        }
        if (t < LCB) s_nrm[t] = __ldg(&g_nrm_lc[g * LCB + t]);
        for (int i = t; i < 512; i += 256) s_w[i] = __ldg(&cw[i]);
        if (t < 16) s_b[t] = __ldg(&cb[t]);
        if (t < 32) s_cnt[t] = 0;
    }
    __syncthreads();

    const int dl = t >> 3, oct = t & 7;
    const int dstRow = isLC ? g * LCB + part * 32 + dl
                            : g * TSB + (part - 6) * 32 + dl;
    float xi[H];
    if (isLC) ld16s(xi, s_enc + (part * 32 + dl) * ROWP);
    else      ld16g(xi, g_ts_enc + dstRow * H);
    float nd = norm16(xi);
    u64 xp[8];
    #pragma unroll
    for (int q = 0; q < 8; q++) xp[q] = pk2(xi[2*q], xi[2*q+1]);

    float T = pass1_T8<256>(xp, nd, s_enc, s_nrm, s_d, oct, t);
    float mv[H];
    select_maxv8<256>(T, s_d, s_v, s_cnt, s_sel, dl, oct, t, mv);

    const int ch0 = oct * 2;
    const float* uPtr = (isLC ? g_u_lc : g_u_ts) + dstRow * H;
    float u0 = __ldg(&uPtr[ch0]), u1 = __ldg(&uPtr[ch0 + 1]);
    float fa = eluf(u0 + mv[ch0]), fb = eluf(u1 + mv[ch0 + 1]);
    s_f[dl * ROWP + ch0] = fa; s_f[dl * ROWP + ch0 + 1] = fb;
    __syncwarp();
    float f[H];
    ld16s(f, s_f + dl * ROWP);

    if (isLC) {
        *(float2*)&g_f1[dstRow * H + ch0] = make_float2(fa, fb);
        float a0 = 0.f, a1 = 0.f;
        #pragma unroll
        for (int i = 0; i < H; i++) {
            a0 = fmaf(f[i], s_w[(H + i) * H + ch0], a0);
            a1 = fmaf(f[i], s_w[(H + i) * H + ch0 + 1], a1);
        }
        *(float2*)&g_v3[dstRow * H + ch0] = make_float2(a0, a1);
        if (oct == 0) g_nrm3[dstRow] = norm16(f);
    } else {
        *(float2*)&g_f2[dstRow * H + ch0] = make_float2(fa, fb);
        float a0 = s_b[ch0], a1 = s_b[ch0 + 1];
        #pragma unroll
        for (int i = 0; i < H; i++) {
            a0 = fmaf(f[i], s_w[i * H + ch0] - s_w[(H + i) * H + ch0], a0);
            a1 = fmaf(f[i], s_w[i * H + ch0 + 1] - s_w[(H + i) * H + ch0 + 1], a1);
        }
        *(float2*)&g_u3[dstRow * H + ch0] = make_float2(a0, a1);
    }
}

// ================= kB: conv3 + pool + head, 16 dst x 8 thr =================
#define B_ENC  0
#define B_V    3840
#define B_NRM  7680
#define B_D    7872
#define B_POOL 10944
#define B_PLD  11264
#define B_H1   11280
#define B_H2   11344
#define B_H3   11376
#define B_H4   11384
#define B_CNT  11388
#define B_SEL  11404
#define B_FLAG 11788
#define B_TOTF 11792   // 47168 bytes

__global__ void __launch_bounds__(128, 4)
kB(const float* __restrict__ w1, const float* __restrict__ b1,
   const float* __restrict__ w2, const float* __restrict__ b2,
   const float* __restrict__ w3, const float* __restrict__ b3,
   const float* __restrict__ w4, const float* __restrict__ b4,
   const float* __restrict__ w5, const float* __restrict__ b5,
   float* __restrict__ out, int out_size)
{
    extern __shared__ float sm[];
    float* s_enc  = sm + B_ENC;
    float* s_v    = sm + B_V;
    float* s_nrm  = sm + B_NRM;
    float* s_d    = sm + B_D;
    float* s_pool = sm + B_POOL;
    float* pooled = sm + B_PLD;
    float* h1s    = sm + B_H1;
    float* h2s    = sm + B_H2;
    float* h3s    = sm + B_H3;
    float* h4s    = sm + B_H4;
    int*   s_cnt  = (int*)(sm + B_CNT);
    int*   s_sel  = (int*)(sm + B_SEL);
    int*   s_flag = (int*)(sm + B_FLAG);

    const int g = blockIdx.x >> 3, qpart = blockIdx.x & 7;
    const int t = threadIdx.x;

    {
        const float4* ge = (const float4*)(g_f1 + g * LCB * H);
        const float4* gv = (const float4*)(g_v3 + g * LCB * H);
        float4* se = (float4*)s_enc; float4* sv = (float4*)s_v;
        #pragma unroll
        for (int i = t; i < LCB * 4; i += 128) {
            int r = i >> 2, c = i & 3;
            se[r * 5 + c] = __ldg(&ge[i]);
            sv[r * 5 + c] = __ldg(&gv[i]);
        }
        for (int i = t; i < LCB; i += 128) s_nrm[i] = __ldg(&g_nrm3[g * LCB + i]);
        if (t < 16) s_cnt[t] = 0;
    }
    __syncthreads();

    const int dl = t >> 3, oct = t & 7;
    const int dstRow = g * TSB + qpart * 16 + dl;
    float xi[H];
    ld16g(xi, g_f2 + dstRow * H);
    float nd = norm16(xi);
    u64 xp[8];
    #pragma unroll
    for (int q = 0; q < 8; q++) xp[q] = pk2(xi[2*q], xi[2*q+1]);

    float T = pass1_T8<128>(xp, nd, s_enc, s_nrm, s_d, oct, t);
    float mv[H];
    select_maxv8<128>(T, s_d, s_v, s_cnt, s_sel, dl, oct, t, mv);

    const int ch0 = oct * 2;
    float u0 = __ldg(&g_u3[dstRow * H + ch0]), u1 = __ldg(&g_u3[dstRow * H + ch0 + 1]);
    s_pool[dl * ROWP + ch0]     = eluf(u0 + mv[ch0]);
    s_pool[dl * ROWP + ch0 + 1] = eluf(u1 + mv[ch0 + 1]);
    __syncthreads();

    if (t < H) {
        float a = 0.f;
        #pragma unroll
        for (int d = 0; d < 16; d++) a += s_pool[d * ROWP + t];
        g_part[(g * 8 + qpart) * H + t] = a;
    }
    __threadfence();
    __syncthreads();
    if (t == 0) {
        int tk = atomicAdd(&g_cnt[g], 1);
        s_flag[0] = (tk == 7);
    }
    __syncthreads();

    if (s_flag[0]) {
        __threadfence();
        if (t < H) {
            const float* pp = g_part + g * 8 * H + t;
            float p01 = pp[0] + pp[H];
            float p23 = pp[2*H] + pp[3*H];
            float p45 = pp[4*H] + pp[5*H];
            float p67 = pp[6*H] + pp[7*H];
            pooled[t] = ((p01 + p23) + (p45 + p67)) * (1.f / (float)TSB);
        }
        __syncthreads();
        if (t < 64) {
            float sv = __ldg(&b1[t]);
            #pragma unroll
            for (int i = 0; i < H; i++) sv += pooled[i] * __ldg(&w1[i * 64 + t]);
            h1s[t] = eluf(sv);
        }
        __syncthreads();
        if (t < 32) {
            float sv = __ldg(&b2[t]);
            #pragma unroll
            for (int i = 0; i < 64; i++) sv += h1s[i] * __ldg(&w2[i * 32 + t]);
            h2s[t] = eluf(sv);
        }
        __syncthreads();
        if (t < 8) {
            float sv = __ldg(&b3[t]);
            #pragma unroll
            for (int i = 0; i < 32; i++) sv += h2s[i] * __ldg(&w3[i * 8 + t]);
            h3s[t] = eluf(sv);
        }
        __syncthreads();
        if (t < 4) {
            float sv = __ldg(&b4[t]);
            #pragma unroll
            for (int i = 0; i < 8; i++) sv += h3s[i] * __ldg(&w4[i * 4 + t]);
            h4s[t] = eluf(sv);
        }
        __syncthreads();
        if (t == 0) {
            float sv = __ldg(&b5[0]);
            #pragma unroll
            for (int i = 0; i < 4; i++) sv += h4s[i] * __ldg(&w5[i]);
            if (g < out_size) out[g] = sv;
            if (NB + g < out_size) out[NB + g] = (float)g;
        }
    }
}

// ==================== launch ====================
extern "C" void kernel_launch(void* const* d_in, const int* in_sizes, int n_in,
                              void* d_out, int out_size)
{
    const float* x_ts = (const float*)d_in[0];
    const float* x_lc = (const float*)d_in[1];
    const float* tw1 = (const float*)d_in[4];
    const float* tb1 = (const float*)d_in[5];
    const float* tw2 = (const float*)d_in[6];
    const float* tb2 = (const float*)d_in[7];
    const float* lw1 = (const float*)d_in[8];
    const float* lb1 = (const float*)d_in[9];
    const float* lw2 = (const float*)d_in[10];
    const float* lb2 = (const float*)d_in[11];
    const float* cw  = (const float*)d_in[12];
    const float* cb  = (const float*)d_in[13];
    const float* w1  = (const float*)d_in[14];
    const float* b1  = (const float*)d_in[15];
    const float* w2  = (const float*)d_in[16];
    const float* b2  = (const float*)d_in[17];
    const float* w3  = (const float*)d_in[18];
    const float* b3  = (const float*)d_in[19];
    const float* w4  = (const float*)d_in[20];
    const float* b4  = (const float*)d_in[21];
    const float* w5  = (const float*)d_in[22];
    const float* b5  = (const float*)d_in[23];

    cudaFuncSetAttribute(kA, cudaFuncAttributeMaxDynamicSharedMemorySize, A_TOTF * 4);
    cudaFuncSetAttribute(kB, cudaFuncAttributeMaxDynamicSharedMemorySize, B_TOTF * 4);

    k_encode<<<((N_TS + N_LC) * 16) / 256, 256>>>(x_ts, x_lc, tw1, tb1, tw2, tb2,
                                                  lw1, lb1, lw2, lb2, cw, cb);
    kA<<<NB * 10, 256, A_TOTF * 4>>>(cw, cb);
    kB<<<NB * 8, 128, B_TOTF * 4>>>(w1, b1, w2, b2, w3, b3, w4, b4, w5, b5,
                                    (float*)d_out, out_size);
}

// round 14
// speedup vs baseline: 1.0948x; 1.0442x over previous
#include <cuda_runtime.h>
#include <math.h>

#define N_TS 8192
#define N_LC 12288
#define NB   64
#define TSB  128
#define LCB  192
#define H    16
#define ROWP 20

typedef unsigned long long u64;

// ---------------- global scratch ----------------
__device__ float g_ts_enc[N_TS * H];
__device__ float g_u_ts [N_TS * H];
__device__ float g_lc_enc[N_LC * H];
__device__ float g_u_lc [N_LC * H];
__device__ float g_v_lc [N_LC * H];
__device__ float g_nrm_lc[N_LC];
__device__ float g_f1  [N_LC * H];
__device__ float g_v3  [N_LC * H];
__device__ float g_nrm3[N_LC];
__device__ float g_f2  [N_TS * H];
__device__ float g_u3  [N_TS * H];
__device__ float g_part[NB * 8 * H];
__device__ int   g_cnt [NB];

// fast ELU: __expf (MUFU EX2) instead of software expm1f; |err| ~1e-6 abs
__device__ __forceinline__ float eluf(float x) { return x > 0.f ? x : __expf(x) - 1.f; }

__device__ __forceinline__ void ld16s(float (&x)[H], const float* p) {
    const float4* p4 = (const float4*)p;
    #pragma unroll
    for (int q = 0; q < 4; q++) {
        float4 v = p4[q];
        x[4*q] = v.x; x[4*q+1] = v.y; x[4*q+2] = v.z; x[4*q+3] = v.w;
    }
}
__device__ __forceinline__ void ld16g(float (&x)[H], const float* p) {
    const float4* p4 = (const float4*)p;
    #pragma unroll
    for (int q = 0; q < 4; q++) {
        float4 v = __ldg(&p4[q]);
        x[4*q] = v.x; x[4*q+1] = v.y; x[4*q+2] = v.z; x[4*q+3] = v.w;
    }
}

// ---------------- packed f32x2 helpers ----------------
__device__ __forceinline__ u64 pk2(float a, float b) {
    u64 r; asm("mov.b64 %0, {%1, %2};" : "=l"(r) : "f"(a), "f"(b)); return r;
}
__device__ __forceinline__ float2 upk2(u64 v) {
    float2 r; asm("mov.b64 {%0, %1}, %2;" : "=f"(r.x), "=f"(r.y) : "l"(v)); return r;
}
__device__ __forceinline__ u64 mul2(u64 a, u64 b) {
    u64 r; asm("mul.rn.f32x2 %0, %1, %2;" : "=l"(r) : "l"(a), "l"(b)); return r;
}
__device__ __forceinline__ u64 fma2(u64 a, u64 b, u64 c) {
    u64 r; asm("fma.rn.f32x2 %0, %1, %2, %3;" : "=l"(r) : "l"(a), "l"(b), "l"(c)); return r;
}

// packed distance: 8 FFMA2 (2 chains of 4) instead of 16 FFMA
__device__ __forceinline__ float distp(const u64 (&xp)[8], float nd,
                                       const float* __restrict__ sp, float nj)
{
    const float4* p4 = (const float4*)sp;
    float4 p0 = p4[0], p1 = p4[1], p2 = p4[2], p3 = p4[3];
    u64 a = mul2(xp[0], pk2(p0.x, p0.y));
    a = fma2(xp[1], pk2(p0.z, p0.w), a);
    a = fma2(xp[2], pk2(p1.x, p1.y), a);
    a = fma2(xp[3], pk2(p1.z, p1.w), a);
    u64 b = mul2(xp[4], pk2(p2.x, p2.y));
    b = fma2(xp[5], pk2(p2.z, p2.w), b);
    b = fma2(xp[6], pk2(p3.x, p3.y), b);
    b = fma2(xp[7], pk2(p3.z, p3.w), b);
    float2 fa = upk2(a), fb = upk2(b);
    float dot = __fadd_rn(__fadd_rn(fa.x, fa.y), __fadd_rn(fb.x, fb.y));
    return fmaf(-2.0f, dot, __fadd_rn(nd, nj));
}

__device__ __forceinline__ float norm16(const float (&x)[H]) {
    float n0 = fmaf(x[0],  x[0],  fmaf(x[1],  x[1],  fmaf(x[2],  x[2],  x[3]  * x[3])));
    float n1 = fmaf(x[4],  x[4],  fmaf(x[5],  x[5],  fmaf(x[6],  x[6],  x[7]  * x[7])));
    float n2 = fmaf(x[8],  x[8],  fmaf(x[9],  x[9],  fmaf(x[10], x[10], x[11] * x[11])));
    float n3 = fmaf(x[12], x[12], fmaf(x[13], x[13], fmaf(x[14], x[14], x[15] * x[15])));
    return (n0 + n1) + (n2 + n3);
}

__device__ __forceinline__ void bitonic16(float (&m)[16]) {
    #pragma unroll
    for (int j = 8; j > 0; j >>= 1) {
        #pragma unroll
        for (int i = 0; i < 16; i++) {
            if ((i & j) == 0) {
                float lo = fminf(m[i], m[i + j]);
                m[i + j] = fmaxf(m[i], m[i + j]);
                m[i] = lo;
            }
        }
    }
}

// 8 threads per dst; growing-depth insertion (exact; upper slots are +inf)
template<int NT>
__device__ __forceinline__ float pass1_T8(const u64 (&xp)[8], float nd,
                                          const float* __restrict__ s_enc,
                                          const float* __restrict__ s_nrm,
                                          float* __restrict__ s_d,
                                          int oct, int t)
{
    float bd[16];
    #pragma unroll
    for (int k = 0; k < 16; k++) bd[k] = 1e30f;
    #pragma unroll
    for (int j = 0; j < 16; j++) {
        int row = (j << 3) | oct;
        float d = distp(xp, nd, s_enc + row * ROWP, s_nrm[row]);
        s_d[j * NT + t] = d;
        #pragma unroll
        for (int k = 0; k <= j; k++) {
            float lo = fminf(d, bd[k]);
            d = fmaxf(d, bd[k]);
            bd[k] = lo;
        }
    }
    #pragma unroll 2
    for (int j = 16; j < 24; j++) {
        int row = (j << 3) | oct;
        float d = distp(xp, nd, s_enc + row * ROWP, s_nrm[row]);
        s_d[j * NT + t] = d;
        #pragma unroll
        for (int k = 0; k < 16; k++) {
            float lo = fminf(d, bd[k]);
            d = fmaxf(d, bd[k]);
            bd[k] = lo;
        }
    }
    float m[16];
    #pragma unroll
    for (int k = 0; k < 16; k++)
        m[k] = fminf(bd[k], __shfl_xor_sync(0xFFFFFFFFu, bd[15 - k], 1));
    bitonic16(m);
    #pragma unroll
    for (int k = 0; k < 16; k++)
        bd[k] = fminf(m[k], __shfl_xor_sync(0xFFFFFFFFu, m[15 - k], 2));
    bitonic16(bd);
    float T = -1e30f;
    #pragma unroll
    for (int k = 0; k < 16; k++)
        T = fmaxf(T, fminf(bd[k], __shfl_xor_sync(0xFFFFFFFFu, bd[15 - k], 4)));
    return T;
}

// pass2: ballot-compaction (no shared atomics), gather v split across the oct, reduce
template<int NT>
__device__ __forceinline__ void select_maxv8(float T,
                                             const float* __restrict__ s_d,
                                             const float* __restrict__ s_v,
                                             int* __restrict__ s_sel,
                                             int dl, int oct, int t, float (&mv)[H])
{
    const unsigned FULL = 0xFFFFFFFFu;
    const int grpShift = t & 24;          // 8-lane group offset within the warp
    const unsigned laneBelow = (1u << oct) - 1u;
    int base = 0;
    #pragma unroll 4
    for (int j = 0; j < 24; j++) {
        float d = s_d[j * NT + t];
        bool sel = (d <= T);
        unsigned m = __ballot_sync(FULL, sel);
        unsigned gm = (m >> grpShift) & 0xFFu;
        if (sel) {
            int pos = base + __popc(gm & laneBelow);
            if (pos < 24) s_sel[dl * 24 + pos] = (j << 3) | oct;
        }
        base += __popc(gm);
    }
    __syncwarp();
    #pragma unroll
    for (int h = 0; h < H; h++) mv[h] = -1e30f;
    int n = base; if (n > 24) n = 24;
    for (int k = oct; k < n; k += 8) {
        int row = s_sel[dl * 24 + k];
        const float4* v4 = (const float4*)(s_v + row * ROWP);
        float4 q0 = v4[0], q1 = v4[1], q2 = v4[2], q3 = v4[3];
        mv[0]  = fmaxf(mv[0],  q0.x); mv[1]  = fmaxf(mv[1],  q0.y);
        mv[2]  = fmaxf(mv[2],  q0.z); mv[3]  = fmaxf(mv[3],  q0.w);
        mv[4]  = fmaxf(mv[4],  q1.x); mv[5]  = fmaxf(mv[5],  q1.y);
        mv[6]  = fmaxf(mv[6],  q1.z); mv[7]  = fmaxf(mv[7],  q1.w);
        mv[8]  = fmaxf(mv[8],  q2.x); mv[9]  = fmaxf(mv[9],  q2.y);
        mv[10] = fmaxf(mv[10], q2.z); mv[11] = fmaxf(mv[11], q2.w);
        mv[12] = fmaxf(mv[12], q3.x); mv[13] = fmaxf(mv[13], q3.y);
        mv[14] = fmaxf(mv[14], q3.z); mv[15] = fmaxf(mv[15], q3.w);
    }
    #pragma unroll
    for (int h = 0; h < H; h++) mv[h] = fmaxf(mv[h], __shfl_xor_sync(FULL, mv[h], 1));
    #pragma unroll
    for (int h = 0; h < H; h++) mv[h] = fmaxf(mv[h], __shfl_xor_sync(FULL, mv[h], 2));
    #pragma unroll
    for (int h = 0; h < H; h++) mv[h] = fmaxf(mv[h], __shfl_xor_sync(FULL, mv[h], 4));
}

// ==================== K0: encoders — lane-per-channel ====================
__global__ void __launch_bounds__(256)
k_encode(const float* __restrict__ x_ts, const float* __restrict__ x_lc,
         const float* __restrict__ tw1, const float* __restrict__ tb1,
         const float* __restrict__ tw2, const float* __restrict__ tb2,
         const float* __restrict__ lw1, const float* __restrict__ lb1,
         const float* __restrict__ lw2, const float* __restrict__ lb2,
         const float* __restrict__ cw,  const float* __restrict__ cb)
{
    __shared__ float s_ew[1280];
    const int t = threadIdx.x;
    // straight-line staging (no if-chain)
    if (t < 96)  s_ew[t]        = __ldg(&tw1[t]);
    if (t < 16)  s_ew[96 + t]   = __ldg(&tb1[t]);
    s_ew[112 + t] = __ldg(&tw2[t]);
    if (t < 16)  s_ew[368 + t]  = __ldg(&tb2[t]);
    if (t < 80)  s_ew[384 + t]  = __ldg(&lw1[t]);
    if (t < 16)  s_ew[464 + t]  = __ldg(&lb1[t]);
    s_ew[480 + t] = __ldg(&lw2[t]);
    if (t < 16)  s_ew[736 + t]  = __ldg(&lb2[t]);
    s_ew[752 + t]  = __ldg(&cw[t]);
    s_ew[1008 + t] = __ldg(&cw[256 + t]);
    if (t < 16)  s_ew[1264 + t] = __ldg(&cb[t]);
    __syncthreads();

    const int gtid = blockIdx.x * 256 + t;
    const int p = gtid >> 4;        // point id
    const int o = gtid & 15;        // channel lane
    if (gtid < NB) g_cnt[gtid] = 0; // reset pool tickets for kB
    const unsigned FULL = 0xFFFFFFFFu;

    if (p < N_TS) {
        float xv = (o < 6) ? __ldg(&x_ts[p * 6 + o]) : 0.f;
        float acc = s_ew[96 + o];
        #pragma unroll
        for (int i = 0; i < 6; i++)
            acc = fmaf(__shfl_sync(FULL, xv, i, 16), s_ew[i * H + o], acc);
        float h1 = eluf(acc);

        acc = s_ew[368 + o];
        #pragma unroll
        for (int i = 0; i < H; i++)
            acc = fmaf(__shfl_sync(FULL, h1, i, 16), s_ew[112 + i * H + o], acc);
        float e = eluf(acc);
        g_ts_enc[p * H + o] = e;

        float uacc = s_ew[1264 + o];
        #pragma unroll
        for (int i = 0; i < H; i++) {
            float ei = __shfl_sync(FULL, e, i, 16);
            uacc = fmaf(ei, s_ew[752 + i * H + o] - s_ew[752 + (H + i) * H + o], uacc);
        }
        g_u_ts[p * H + o] = uacc;
    } else if (p < N_TS + N_LC) {
        const int id = p - N_TS;
        float xv = (o < 5) ? __ldg(&x_lc[id * 5 + o]) : 0.f;
        float acc = s_ew[464 + o];
        #pragma unroll
        for (int i = 0; i < 5; i++)
            acc = fmaf(__shfl_sync(FULL, xv, i, 16), s_ew[384 + i * H + o], acc);
        float h1 = eluf(acc);

        acc = s_ew[736 + o];
        #pragma unroll
        for (int i = 0; i < H; i++)
            acc = fmaf(__shfl_sync(FULL, h1, i, 16), s_ew[480 + i * H + o], acc);
        float e = eluf(acc);
        g_lc_enc[id * H + o] = e;

        float r = e * e;
        r += __shfl_xor_sync(FULL, r, 1, 16);
        r += __shfl_xor_sync(FULL, r, 2, 16);
        r += __shfl_xor_sync(FULL, r, 4, 16);
        r += __shfl_xor_sync(FULL, r, 8, 16);
        if (o == 0) g_nrm_lc[id] = r;

        float uacc = s_ew[1264 + o], vacc = 0.f;
        #pragma unroll
        for (int i = 0; i < H; i++) {
            float ei = __shfl_sync(FULL, e, i, 16);
            float wt = s_ew[752 + i * H + o];
            float wb = s_ew[752 + (H + i) * H + o];
            uacc = fmaf(ei, wt - wb, uacc);
            vacc = fmaf(ei, wb, vacc);
        }
        g_u_lc[id * H + o] = uacc;
        g_v_lc[id * H + o] = vacc;
    }
}

// ================= kA: conv1 + conv2 (+u3/v3 fused), 32 dst x 8 thr =================
#define A_ENC 0
#define A_V   3840
#define A_NRM 7680
#define A_W   7872
#define A_B   8384
#define A_D   8400
#define A_F   14544
#define A_CNT 15184
#define A_SEL 15216
#define A_TOTF 15984   // 63936 bytes

__global__ void __launch_bounds__(256, 3)
kA(const float* __restrict__ cw, const float* __restrict__ cb)
{
    extern __shared__ float sm[];
    float* s_enc = sm + A_ENC;
    float* s_v   = sm + A_V;
    float* s_nrm = sm + A_NRM;
    float* s_w   = sm + A_W;
    float* s_b   = sm + A_B;
    float* s_d   = sm + A_D;
    float* s_f   = sm + A_F;
    int*   s_sel = (int*)(sm + A_SEL);

    const int g = blockIdx.x / 10, part = blockIdx.x % 10;
    const int t = threadIdx.x;
    const bool isLC = part < 6;

    {
        const float4* ge = (const float4*)(g_lc_enc + g * LCB * H);
        const float4* gv = (const float4*)(g_v_lc  + g * LCB * H);
        float4* se = (float4*)s_enc; float4* sv = (float4*)s_v;
        #pragma unroll
        for (int i = t; i < LCB * 4; i += 256) {
            int r = i >> 2, c = i & 3;
            se[r * 5 + c] = __ldg(&ge[i]);
            sv[r * 5 + c] = __ldg(&gv[i]);
        }
        if (t < LCB) s_nrm[t] = __ldg(&g_nrm_lc[g * LCB + t]);
        for (int i = t; i < 512; i += 256) s_w[i] = __ldg(&cw[i]);
        if (t < 16) s_b[t] = __ldg(&cb[t]);
    }
    __syncthreads();

    const int dl = t >> 3, oct = t & 7;
    const int dstRow = isLC ? g * LCB + part * 32 + dl
                            : g * TSB + (part - 6) * 32 + dl;
    float xi[H];
    if (isLC) ld16s(xi, s_enc + (part * 32 + dl) * ROWP);
    else      ld16g(xi, g_ts_enc + dstRow * H);
    float nd = norm16(xi);
    u64 xp[8];
    #pragma unroll
    for (int q = 0; q < 8; q++) xp[q] = pk2(xi[2*q], xi[2*q+1]);

    float T = pass1_T8<256>(xp, nd, s_enc, s_nrm, s_d, oct, t);
    float mv[H];
    select_maxv8<256>(T, s_d, s_v, s_sel, dl, oct, t, mv);

    const int ch0 = oct * 2;
    const float* uPtr = (isLC ? g_u_lc : g_u_ts) + dstRow * H;
    float u0 = __ldg(&uPtr[ch0]), u1 = __ldg(&uPtr[ch0 + 1]);
    float fa = eluf(u0 + mv[ch0]), fb = eluf(u1 + mv[ch0 + 1]);
    s_f[dl * ROWP + ch0] = fa; s_f[dl * ROWP + ch0 + 1] = fb;
    __syncwarp();
    float f[H];
    ld16s(f, s_f + dl * ROWP);

    if (isLC) {
        *(float2*)&g_f1[dstRow * H + ch0] = make_float2(fa, fb);
        float a0 = 0.f, a1 = 0.f;
        #pragma unroll
        for (int i = 0; i < H; i++) {
            a0 = fmaf(f[i], s_w[(H + i) * H + ch0], a0);
            a1 = fmaf(f[i], s_w[(H + i) * H + ch0 + 1], a1);
        }
        *(float2*)&g_v3[dstRow * H + ch0] = make_float2(a0, a1);
        if (oct == 0) g_nrm3[dstRow] = norm16(f);
    } else {
        *(float2*)&g_f2[dstRow * H + ch0] = make_float2(fa, fb);
        float a0 = s_b[ch0], a1 = s_b[ch0 + 1];
        #pragma unroll
        for (int i = 0; i < H; i++) {
            a0 = fmaf(f[i], s_w[i * H + ch0] - s_w[(H + i) * H + ch0], a0);
            a1 = fmaf(f[i], s_w[i * H + ch0 + 1] - s_w[(H + i) * H + ch0 + 1], a1);
        }
        *(float2*)&g_u3[dstRow * H + ch0] = make_float2(a0, a1);
    }
}

// ================= kB: conv3 + pool + head, 16 dst x 8 thr =================
#define B_ENC  0
#define B_V    3840
#define B_NRM  7680
#define B_D    7872
#define B_POOL 10944
#define B_PLD  11264
#define B_H1   11280
#define B_H2   11344
#define B_H3   11376
#define B_H4   11384
#define B_CNT  11388
#define B_SEL  11404
#define B_FLAG 11788
#define B_TOTF 11792   // 47168 bytes

__global__ void __launch_bounds__(128, 4)
kB(const float* __restrict__ w1, const float* __restrict__ b1,
   const float* __restrict__ w2, const float* __restrict__ b2,
   const float* __restrict__ w3, const float* __restrict__ b3,
   const float* __restrict__ w4, const float* __restrict__ b4,
   const float* __restrict__ w5, const float* __restrict__ b5,
   float* __restrict__ out, int out_size)
{
    extern __shared__ float sm[];
    float* s_enc  = sm + B_ENC;
    float* s_v    = sm + B_V;
    float* s_nrm  = sm + B_NRM;
    float* s_d    = sm + B_D;
    float* s_pool = sm + B_POOL;
    float* pooled = sm + B_PLD;
    float* h1s    = sm + B_H1;
    float* h2s    = sm + B_H2;
    float* h3s    = sm + B_H3;
    float* h4s    = sm + B_H4;
    int*   s_sel  = (int*)(sm + B_SEL);
    int*   s_flag = (int*)(sm + B_FLAG);

    const int g = blockIdx.x >> 3, qpart = blockIdx.x & 7;
    const int t = threadIdx.x;

    {
        const float4* ge = (const float4*)(g_f1 + g * LCB * H);
        const float4* gv = (const float4*)(g_v3 + g * LCB * H);
        float4* se = (float4*)s_enc; float4* sv = (float4*)s_v;
        #pragma unroll
        for (int i = t; i < LCB * 4; i += 128) {
            int r = i >> 2, c = i & 3;
            se[r * 5 + c] = __ldg(&ge[i]);
            sv[r * 5 + c] = __ldg(&gv[i]);
        }
        for (int i = t; i < LCB; i += 128) s_nrm[i] = __ldg(&g_nrm3[g * LCB + i]);
    }
    __syncthreads();

    const int dl = t >> 3, oct = t & 7;
    const int dstRow = g * TSB + qpart * 16 + dl;
    float xi[H];
    ld16g(xi, g_f2 + dstRow * H);
    float nd = norm16(xi);
    u64 xp[8];
    #pragma unroll
    for (int q = 0; q < 8; q++) xp[q] = pk2(xi[2*q], xi[2*q+1]);

    float T = pass1_T8<128>(xp, nd, s_enc, s_nrm, s_d, oct, t);
    float mv[H];
    select_maxv8<128>(T, s_d, s_v, s_sel, dl, oct, t, mv);

    const int ch0 = oct * 2;
    float u0 = __ldg(&g_u3[dstRow * H + ch0]), u1 = __ldg(&g_u3[dstRow * H + ch0 + 1]);
    s_pool[dl * ROWP + ch0]     = eluf(u0 + mv[ch0]);
    s_pool[dl * ROWP + ch0 + 1] = eluf(u1 + mv[ch0 + 1]);
    __syncthreads();

    if (t < H) {
        float a = 0.f;
        #pragma unroll
        for (int d = 0; d < 16; d++) a += s_pool[d * ROWP + t];
        g_part[(g * 8 + qpart) * H + t] = a;
    }
    __threadfence();
    __syncthreads();
    if (t == 0) {
        int tk = atomicAdd(&g_cnt[g], 1);
        s_flag[0] = (tk == 7);
    }
    __syncthreads();

    if (s_flag[0]) {
        __threadfence();
        if (t < H) {
            const float* pp = g_part + g * 8 * H + t;
            float p01 = pp[0] + pp[H];
            float p23 = pp[2*H] + pp[3*H];
            float p45 = pp[4*H] + pp[5*H];
            float p67 = pp[6*H] + pp[7*H];
            pooled[t] = ((p01 + p23) + (p45 + p67)) * (1.f / (float)TSB);
        }
        __syncthreads();
        if (t < 64) {
            float sv = __ldg(&b1[t]);
            #pragma unroll
            for (int i = 0; i < H; i++) sv += pooled[i] * __ldg(&w1[i * 64 + t]);
            h1s[t] = eluf(sv);
        }
        __syncthreads();
        if (t < 32) {
            float sv = __ldg(&b2[t]);
            #pragma unroll
            for (int i = 0; i < 64; i++) sv += h1s[i] * __ldg(&w2[i * 32 + t]);
            h2s[t] = eluf(sv);
        }
        __syncthreads();
        if (t < 8) {
            float sv = __ldg(&b3[t]);
            #pragma unroll
            for (int i = 0; i < 32; i++) sv += h2s[i] * __ldg(&w3[i * 8 + t]);
            h3s[t] = eluf(sv);
        }
        __syncthreads();
        if (t < 4) {
            float sv = __ldg(&b4[t]);
            #pragma unroll
            for (int i = 0; i < 8; i++) sv += h3s[i] * __ldg(&w4[i * 4 + t]);
            h4s[t] = eluf(sv);
        }
        __syncthreads();
        if (t == 0) {
            float sv = __ldg(&b5[0]);
            #pragma unroll
            for (int i = 0; i < 4; i++) sv += h4s[i] * __ldg(&w5[i]);
            if (g < out_size) out[g] = sv;
            if (NB + g < out_size) out[NB + g] = (float)g;
        }
    }
}

// ==================== launch ====================
extern "C" void kernel_launch(void* const* d_in, const int* in_sizes, int n_in,
                              void* d_out, int out_size)
{
    const float* x_ts = (const float*)d_in[0];
    const float* x_lc = (const float*)d_in[1];
    const float* tw1 = (const float*)d_in[4];
    const float* tb1 = (const float*)d_in[5];
    const float* tw2 = (const float*)d_in[6];
    const float* tb2 = (const float*)d_in[7];
    const float* lw1 = (const float*)d_in[8];
    const float* lb1 = (const float*)d_in[9];
    const float* lw2 = (const float*)d_in[10];
    const float* lb2 = (const float*)d_in[11];
    const float* cw  = (const float*)d_in[12];
    const float* cb  = (const float*)d_in[13];
    const float* w1  = (const float*)d_in[14];
    const float* b1  = (const float*)d_in[15];
    const float* w2  = (const float*)d_in[16];
    const float* b2  = (const float*)d_in[17];
    const float* w3  = (const float*)d_in[18];
    const float* b3  = (const float*)d_in[19];
    const float* w4  = (const float*)d_in[20];
    const float* b4  = (const float*)d_in[21];
    const float* w5  = (const float*)d_in[22];
    const float* b5  = (const float*)d_in[23];

    cudaFuncSetAttribute(kA, cudaFuncAttributeMaxDynamicSharedMemorySize, A_TOTF * 4);
    cudaFuncSetAttribute(kB, cudaFuncAttributeMaxDynamicSharedMemorySize, B_TOTF * 4);

    k_encode<<<((N_TS + N_LC) * 16) / 256, 256>>>(x_ts, x_lc, tw1, tb1, tw2, tb2,
                                                  lw1, lb1, lw2, lb2, cw, cb);
    kA<<<NB * 10, 256, A_TOTF * 4>>>(cw, cb);
    kB<<<NB * 8, 128, B_TOTF * 4>>>(w1, b1, w2, b2, w3, b3, w4, b4, w5, b5,
                                    (float*)d_out, out_size);
}